// round 1
// baseline (speedup 1.0000x reference)
#include <cuda_runtime.h>
#include <math.h>
#include <stdint.h>

#define N_LEVELS 16
#define LOG2_HASHMAP_SIZE 19
#define HASH_MASK ((1u << LOG2_HASHMAP_SIZE) - 1u)
#define TABLE_ENTRIES (1u << LOG2_HASHMAP_SIZE)
#define N_POINTS 1048576
#define PRIME_Y 2654435761u
#define PRIME_Z 805459861u

struct Res16 { float r[16]; };

// Thread layout: tid & 15 = level, tid >> 4 = point-within-block.
// Block = 256 threads = 16 points x 16 levels.
__global__ void __launch_bounds__(256, 8)
hash_embed_kernel(const float* __restrict__ x,
                  const float* __restrict__ tables,
                  float2* __restrict__ out,
                  Res16 R)
{
    __shared__ float sx[16 * 3];

    const int base_pt = blockIdx.x * 16;
    if (threadIdx.x < 48) {
        sx[threadIdx.x] = x[base_pt * 3 + threadIdx.x];
    }
    __syncthreads();

    const int level = threadIdx.x & 15;
    const int lp    = threadIdx.x >> 4;
    const int p     = base_pt + lp;

    const float px = sx[lp * 3 + 0];
    const float py = sx[lp * 3 + 1];
    const float pz = sx[lp * 3 + 2];

    const float res  = R.r[level];
    const float grid = 2.0f / res;              // (BOX_MAX - BOX_MIN) / resolution

    // bl = floor((x - BOX_MIN)/grid); BOX_MIN = -1. Must be bit-exact vs reference:
    // plain IEEE add + div + floor (no fast-math on this path).
    const float fx = (px + 1.0f) / grid;
    const float fy = (py + 1.0f) / grid;
    const float fz = (pz + 1.0f) / grid;
    const float bxf = floorf(fx);
    const float byf = floorf(fy);
    const float bzf = floorf(fz);
    const int bx = (int)bxf;
    const int by = (int)byf;
    const int bz = (int)bzf;

    // Interp weights: w = (x - vmin)/(vmax - vmin). Tolerance-insensitive (1e-3).
    const float vminx = bxf * grid - 1.0f;
    const float vminy = byf * grid - 1.0f;
    const float vminz = bzf * grid - 1.0f;
    const float wx = (px - vminx) / ((vminx + grid) - vminx);
    const float wy = (py - vminy) / ((vminy + grid) - vminy);
    const float wz = (pz - vminz) / ((vminz + grid) - vminz);

    // Hash components (prime_x = 1).
    const uint32_t hx0 = (uint32_t)bx;
    const uint32_t hx1 = (uint32_t)(bx + 1);
    const uint32_t hy0 = (uint32_t)by * PRIME_Y;
    const uint32_t hy1 = (uint32_t)(by + 1) * PRIME_Y;
    const uint32_t hz0 = (uint32_t)bz * PRIME_Z;
    const uint32_t hz1 = (uint32_t)(bz + 1) * PRIME_Z;

    const float2* __restrict__ tab =
        (const float2*)tables + ((size_t)level << LOG2_HASHMAP_SIZE);

    // 8 independent gathers (MLP=8). Offset bit layout: (xbit, ybit, zbit).
    const float2 v000 = __ldg(&tab[(hx0 ^ hy0 ^ hz0) & HASH_MASK]);
    const float2 v001 = __ldg(&tab[(hx0 ^ hy0 ^ hz1) & HASH_MASK]);
    const float2 v010 = __ldg(&tab[(hx0 ^ hy1 ^ hz0) & HASH_MASK]);
    const float2 v011 = __ldg(&tab[(hx0 ^ hy1 ^ hz1) & HASH_MASK]);
    const float2 v100 = __ldg(&tab[(hx1 ^ hy0 ^ hz0) & HASH_MASK]);
    const float2 v101 = __ldg(&tab[(hx1 ^ hy0 ^ hz1) & HASH_MASK]);
    const float2 v110 = __ldg(&tab[(hx1 ^ hy1 ^ hz0) & HASH_MASK]);
    const float2 v111 = __ldg(&tab[(hx1 ^ hy1 ^ hz1) & HASH_MASK]);

    const float owx = 1.0f - wx;
    const float owy = 1.0f - wy;
    const float owz = 1.0f - wz;

    // x-interp (c00: y=0,z=0 ; c01: y=0,z=1 ; c10: y=1,z=0 ; c11: y=1,z=1)
    float2 c00, c01, c10, c11;
    c00.x = v000.x * owx + v100.x * wx;  c00.y = v000.y * owx + v100.y * wx;
    c01.x = v001.x * owx + v101.x * wx;  c01.y = v001.y * owx + v101.y * wx;
    c10.x = v010.x * owx + v110.x * wx;  c10.y = v010.y * owx + v110.y * wx;
    c11.x = v011.x * owx + v111.x * wx;  c11.y = v011.y * owx + v111.y * wx;

    // y-interp
    float2 c0, c1;
    c0.x = c00.x * owy + c10.x * wy;  c0.y = c00.y * owy + c10.y * wy;
    c1.x = c01.x * owy + c11.x * wy;  c1.y = c01.y * owy + c11.y * wy;

    // z-interp
    float2 r2;
    r2.x = c0.x * owz + c1.x * wz;
    r2.y = c0.y * owz + c1.y * wz;

    // out[p][level] as float2 -> 16 lanes write one contiguous 128B line per point
    out[(size_t)p * N_LEVELS + level] = r2;
}

extern "C" void kernel_launch(void* const* d_in, const int* in_sizes, int n_in,
                              void* d_out, int out_size)
{
    const float* x      = (const float*)d_in[0];
    const float* tables = (const float*)d_in[1];
    float2* out         = (float2*)d_out;

    // Replicate numpy's RESOLUTIONS computation exactly (double libm, then floor).
    Res16 R;
    const double b = exp((log(512.0) - log(16.0)) / 15.0);
    for (int i = 0; i < 16; i++) {
        R.r[i] = (float)floor(16.0 * pow(b, (double)i));
    }

    const int blocks = N_POINTS / 16;  // 65536 blocks x 256 threads
    hash_embed_kernel<<<blocks, 256>>>(x, tables, out, R);
}

// round 2
// speedup vs baseline: 1.5478x; 1.5478x over previous
#include <cuda_runtime.h>
#include <math.h>
#include <stdint.h>

#define N_LEVELS 16
#define LOG2_HASHMAP_SIZE 19
#define HASH_MASK ((1u << LOG2_HASHMAP_SIZE) - 1u)
#define N_POINTS 1048576
#define PRIME_Y 2654435761u
#define PRIME_Z 805459861u
#define N_BINS 32768          // 32^3 spatial bins over [0,1]^3

struct Res16 { float r[16]; };

// Scratch (no cudaMalloc allowed): sorted points + orig index packed in .w
__device__ float4       g_xs4[N_POINTS];     // 16 MB
__device__ unsigned int g_hist[N_BINS];      // counts -> exclusive offsets -> cursors

__device__ __forceinline__ int bin_key(float px, float py, float pz) {
    int bx = (int)(px * 32.0f); bx = bx < 0 ? 0 : (bx > 31 ? 31 : bx);
    int by = (int)(py * 32.0f); by = by < 0 ? 0 : (by > 31 ? 31 : by);
    int bz = (int)(pz * 32.0f); bz = bz < 0 ? 0 : (bz > 31 ? 31 : bz);
    return (bx << 10) | (by << 5) | bz;
}

__global__ void zero_hist_kernel() {
    int i = blockIdx.x * blockDim.x + threadIdx.x;
    if (i < N_BINS) g_hist[i] = 0u;
}

__global__ void hist_kernel(const float* __restrict__ x) {
    int i = blockIdx.x * blockDim.x + threadIdx.x;
    if (i >= N_POINTS) return;
    float px = x[3 * i], py = x[3 * i + 1], pz = x[3 * i + 2];
    atomicAdd(&g_hist[bin_key(px, py, pz)], 1u);
}

// Single-block exclusive scan over 32768 bins (1024 threads x 32 bins each).
__global__ void scan_kernel() {
    __shared__ unsigned int s[1024];
    int t = threadIdx.x;
    unsigned int local[32];
    unsigned int sum = 0;
#pragma unroll
    for (int i = 0; i < 32; i++) { local[i] = g_hist[t * 32 + i]; sum += local[i]; }
    s[t] = sum;
    __syncthreads();
    for (int off = 1; off < 1024; off <<= 1) {
        unsigned int v = (t >= off) ? s[t - off] : 0u;
        __syncthreads();
        s[t] += v;
        __syncthreads();
    }
    unsigned int run = (t == 0) ? 0u : s[t - 1];
#pragma unroll
    for (int i = 0; i < 32; i++) { g_hist[t * 32 + i] = run; run += local[i]; }
}

__global__ void scatter_kernel(const float* __restrict__ x) {
    int i = blockIdx.x * blockDim.x + threadIdx.x;
    if (i >= N_POINTS) return;
    float px = x[3 * i], py = x[3 * i + 1], pz = x[3 * i + 2];
    unsigned int r = atomicAdd(&g_hist[bin_key(px, py, pz)], 1u);
    g_xs4[r] = make_float4(px, py, pz, __int_as_float(i));
}

// Main: block = 512 threads = 16 warps. Warp w handles level w for 32
// spatially-adjacent (sorted) points -> coarse-level gathers coalesce.
__global__ void __launch_bounds__(512)
hash_embed_kernel(const float* __restrict__ tables,
                  float2* __restrict__ out,
                  Res16 R)
{
    __shared__ float2 s_out[32][17];   // [point][level], padded row
    __shared__ int    s_idx[32];

    const int warp = threadIdx.x >> 5;   // = level
    const int lane = threadIdx.x & 31;   // = point within block
    const int base = blockIdx.x * 32;

    const float4 pv = g_xs4[base + lane];
    const float px = pv.x, py = pv.y, pz = pv.z;
    if (warp == 0) s_idx[lane] = __float_as_int(pv.w);

    const int level = warp;
    const float res  = R.r[level];
    const float grid = 2.0f / res;   // fp32, matches reference

    // bl = floor((x - BOX_MIN)/grid), BOX_MIN = -1. Bit-exact IEEE path.
    const float fx = (px + 1.0f) / grid;
    const float fy = (py + 1.0f) / grid;
    const float fz = (pz + 1.0f) / grid;
    const float bxf = floorf(fx);
    const float byf = floorf(fy);
    const float bzf = floorf(fz);
    const int bx = (int)bxf;
    const int by = (int)byf;
    const int bz = (int)bzf;

    const float vminx = bxf * grid - 1.0f;
    const float vminy = byf * grid - 1.0f;
    const float vminz = bzf * grid - 1.0f;
    const float wx = (px - vminx) / ((vminx + grid) - vminx);
    const float wy = (py - vminy) / ((vminy + grid) - vminy);
    const float wz = (pz - vminz) / ((vminz + grid) - vminz);

    const uint32_t hx0 = (uint32_t)bx;
    const uint32_t hx1 = (uint32_t)(bx + 1);
    const uint32_t hy0 = (uint32_t)by * PRIME_Y;
    const uint32_t hy1 = (uint32_t)(by + 1) * PRIME_Y;
    const uint32_t hz0 = (uint32_t)bz * PRIME_Z;
    const uint32_t hz1 = (uint32_t)(bz + 1) * PRIME_Z;

    const float2* __restrict__ tab =
        (const float2*)tables + ((size_t)level << LOG2_HASHMAP_SIZE);

    const float2 v000 = __ldg(&tab[(hx0 ^ hy0 ^ hz0) & HASH_MASK]);
    const float2 v001 = __ldg(&tab[(hx0 ^ hy0 ^ hz1) & HASH_MASK]);
    const float2 v010 = __ldg(&tab[(hx0 ^ hy1 ^ hz0) & HASH_MASK]);
    const float2 v011 = __ldg(&tab[(hx0 ^ hy1 ^ hz1) & HASH_MASK]);
    const float2 v100 = __ldg(&tab[(hx1 ^ hy0 ^ hz0) & HASH_MASK]);
    const float2 v101 = __ldg(&tab[(hx1 ^ hy0 ^ hz1) & HASH_MASK]);
    const float2 v110 = __ldg(&tab[(hx1 ^ hy1 ^ hz0) & HASH_MASK]);
    const float2 v111 = __ldg(&tab[(hx1 ^ hy1 ^ hz1) & HASH_MASK]);

    const float owx = 1.0f - wx;
    const float owy = 1.0f - wy;
    const float owz = 1.0f - wz;

    float2 c00, c01, c10, c11;
    c00.x = v000.x * owx + v100.x * wx;  c00.y = v000.y * owx + v100.y * wx;
    c01.x = v001.x * owx + v101.x * wx;  c01.y = v001.y * owx + v101.y * wx;
    c10.x = v010.x * owx + v110.x * wx;  c10.y = v010.y * owx + v110.y * wx;
    c11.x = v011.x * owx + v111.x * wx;  c11.y = v011.y * owx + v111.y * wx;

    float2 c0, c1;
    c0.x = c00.x * owy + c10.x * wy;  c0.y = c00.y * owy + c10.y * wy;
    c1.x = c01.x * owy + c11.x * wy;  c1.y = c01.y * owy + c11.y * wy;

    float2 r2;
    r2.x = c0.x * owz + c1.x * wz;
    r2.y = c0.y * owz + c1.y * wz;

    s_out[lane][warp] = r2;
    __syncthreads();

    // Coalesced writeback: 16 consecutive threads emit one point's 128B row.
    const int pt  = threadIdx.x >> 4;
    const int lev = threadIdx.x & 15;
    out[(size_t)s_idx[pt] * N_LEVELS + lev] = s_out[pt][lev];
}

extern "C" void kernel_launch(void* const* d_in, const int* in_sizes, int n_in,
                              void* d_out, int out_size)
{
    const float* x      = (const float*)d_in[0];
    const float* tables = (const float*)d_in[1];
    float2* out         = (float2*)d_out;

    // Replicate numpy's RESOLUTIONS computation exactly (double libm, floor).
    Res16 R;
    const double b = exp((log(512.0) - log(16.0)) / 15.0);
    for (int i = 0; i < 16; i++) {
        R.r[i] = (float)floor(16.0 * pow(b, (double)i));
    }

    zero_hist_kernel<<<N_BINS / 1024, 1024>>>();
    hist_kernel<<<N_POINTS / 256, 256>>>(x);
    scan_kernel<<<1, 1024>>>();
    scatter_kernel<<<N_POINTS / 256, 256>>>(x);
    hash_embed_kernel<<<N_POINTS / 32, 512>>>(tables, out, R);
}